// round 16
// baseline (speedup 1.0000x reference)
#include <cuda_runtime.h>
#include <cuda_fp16.h>
#include <cstdint>

#define BB 8
#define CC 256
#define SS 2304

#define BM 128
#define BN 128
#define BKK 32
#define KITERS (CC / BKK)   // 8
#define NTILE 9             // n-tiles walked per GEMM CTA
#define TOTAL_IT (NTILE * KITERS)   // 72

// A region: 128 rows x 256 ch fp16 = 512B data/row, +16B pad
#define ROWA 528
#define A_BYTES (BM * ROWA)              // 67584
// B stage: 128 rows x 32 ch fp16 = 64B/row padded to 80B
#define ROWB 80
#define STG_B (BN * ROWB)                // 10240
#define NSTAGE 4
#define OFF_A 0
#define OFF_B A_BYTES
#define SMEM_TOTAL (A_BYTES + NSTAGE * STG_B)   // 108544 (x2 CTAs/SM)

// fused-grid layout: per batch 144 prep CTAs then 36 GEMM CTAs
#define PREP_PER_BATCH 144               // 72 src + 72 dst (32-wide s tiles)
#define GEMM_PER_BATCH 36                // 2 n-halves x 18 m-tiles
#define PER_BATCH (PREP_PER_BATCH + GEMM_PER_BATCH)   // 180
#define GRID_TOTAL (BB * PER_BATCH)      // 1440

// ---------------- scratch (__device__ globals; no cudaMalloc allowed) ------
__device__ __half g_A[(size_t)BB * SS * CC];
__device__ __half g_B[(size_t)BB * SS * CC];
__device__ int g_done[BB];               // monotone prep-completion counters

// ---------------- PTX helpers (base ISA only) -------------------------------
__device__ __forceinline__ uint32_t smem_u32(const void* p) {
    uint32_t a;
    asm("{ .reg .u64 t; cvta.to.shared.u64 t, %1; cvt.u32.u64 %0, t; }"
        : "=r"(a) : "l"(p));
    return a;
}
__device__ __forceinline__ void cpasync16(uint32_t dst, const void* src) {
    asm volatile("cp.async.cg.shared.global [%0], [%1], 16;"
                 :: "r"(dst), "l"(src) : "memory");
}
#define CP_COMMIT() asm volatile("cp.async.commit_group;" ::: "memory")
#define CP_WAIT(n)  asm volatile("cp.async.wait_group %0;" :: "n"(n) : "memory")

__device__ __forceinline__ void ldsm_x4(uint32_t* r, uint32_t addr) {
    asm volatile("ldmatrix.sync.aligned.m8n8.x4.shared.b16 {%0,%1,%2,%3}, [%4];"
                 : "=r"(r[0]), "=r"(r[1]), "=r"(r[2]), "=r"(r[3]) : "r"(addr));
}
__device__ __forceinline__ void mma16816(float* d, const uint32_t* a,
                                         uint32_t b0, uint32_t b1) {
    asm volatile(
        "mma.sync.aligned.m16n8k16.row.col.f32.f16.f16.f32 "
        "{%0,%1,%2,%3}, {%4,%5,%6,%7}, {%8,%9}, {%0,%1,%2,%3};"
        : "+f"(d[0]), "+f"(d[1]), "+f"(d[2]), "+f"(d[3])
        : "r"(a[0]), "r"(a[1]), "r"(a[2]), "r"(a[3]), "r"(b0), "r"(b1));
}

// ---------------------------------------------------------------------------
// Fused kernel: per batch, 144 prep CTAs (transpose+normalize+fp16) signal a
// device counter; 36 GEMM CTAs spin on it, then run the persistent-n HMMA
// GEMM. 288 GEMM CTAs < 296 slots -> prep always schedulable (no deadlock).
// ---------------------------------------------------------------------------
__global__ void __launch_bounds__(256, 2)
fused_kernel(const float* __restrict__ src, const float* __restrict__ dst,
             float* __restrict__ out) {
    extern __shared__ char smem[];
    const int bid   = blockIdx.x;
    const int batch = bid / PER_BATCH;
    const int r     = bid % PER_BATCH;
    const int tid   = threadIdx.x;

    if (r < PREP_PER_BATCH) {
        // =================== PREP path (R11-style, 32-wide s tile) =========
        float* tile = (float*)smem;            // [CC][33]
        const int which = r / 72;              // 0 = src -> g_A, 1 = dst -> g_B
        const int s0 = (r % 72) * 32;
        const float* in = which ? dst : src;
        __half* outp = which ? g_B : g_A;
        const int tx = tid & 31, ty = tid >> 5;

        const float* p = in + (size_t)batch * CC * SS + s0 + tx;
#pragma unroll
        for (int i = 0; i < 32; ++i)
            tile[(ty + i * 8) * 33 + tx] = p[(size_t)(ty + i * 8) * SS];
        __syncthreads();

        const int s_local = tid >> 3;
        const int cg = tid & 7;

        float v[32];
        float sq = 0.0f;
#pragma unroll
        for (int t = 0; t < 8; ++t)
#pragma unroll
            for (int j = 0; j < 4; ++j) {
                float x = tile[(t * 32 + cg * 4 + j) * 33 + s_local];
                v[t * 4 + j] = x;
                sq = fmaf(x, x, sq);
            }
        sq += __shfl_xor_sync(0xffffffffu, sq, 1);
        sq += __shfl_xor_sync(0xffffffffu, sq, 2);
        sq += __shfl_xor_sync(0xffffffffu, sq, 4);
        const float inv = rsqrtf(sq);

        __half* orow = outp + ((size_t)batch * SS + s0 + s_local) * CC + cg * 4;
#pragma unroll
        for (int t = 0; t < 8; ++t) {
            __half2 h01 = __floats2half2_rn(v[t * 4 + 0] * inv, v[t * 4 + 1] * inv);
            __half2 h23 = __floats2half2_rn(v[t * 4 + 2] * inv, v[t * 4 + 3] * inv);
            uint2 pack = make_uint2(*(uint32_t*)&h01, *(uint32_t*)&h23);
            *(uint2*)&orow[t * 32] = pack;
        }

        // signal completion (release)
        __threadfence();
        __syncthreads();
        if (tid == 0)
            asm volatile("red.release.gpu.global.add.s32 [%0], 1;"
                         :: "l"(&g_done[batch]) : "memory");
        return;
    }

    // =================== GEMM path (persistent-n, R14/15 core) =============
    {
        const int g = r - PREP_PER_BATCH;      // 0..35
        const int n_half = g / 18;
        const int m_tile = g % 18;

        // wait for this batch's prep (monotone counter; instant on replays)
        if (tid == 0) {
            int v;
            do {
                asm volatile("ld.acquire.gpu.global.s32 %0, [%1];"
                             : "=r"(v) : "l"(&g_done[batch]) : "memory");
                if (v >= PREP_PER_BATCH) break;
                __nanosleep(64);
            } while (true);
        }
        __syncthreads();

        uint32_t sb = smem_u32(smem);
        const int lane = tid & 31;
        const int wid  = tid >> 5;
        const int b      = batch;
        const int m0     = m_tile * BM;
        const int n_base = n_half * (NTILE * BN);   // 0 or 1152

        const char* gA = (const char*)(g_A + (size_t)b * SS * CC);
        const char* gB = (const char*)(g_B + (size_t)b * SS * CC);

        // ---- A fill (once): 4096 x 16B chunks, 16/thread
#pragma unroll
        for (int i = 0; i < 16; ++i) {
            int u = tid + i * 256;
            int row = u >> 5, ch = u & 31;
            size_t go = ((size_t)(m0 + row) * CC) * 2 + ch * 16;
            cpasync16(sb + OFF_A + (uint32_t)(row * ROWA + ch * 16), gA + go);
        }
        CP_COMMIT();

        auto load_stageB = [&](int st, int it) {
            uint32_t sbase = sb + OFF_B + (uint32_t)st * STG_B;
            int n0t = n_base + (it >> 3) * BN;
            int c0  = (it & 7) * BKK;
#pragma unroll
            for (int i = 0; i < 2; ++i) {
                int u = tid + i * 256;
                int row = u >> 2, ch = u & 3;
                size_t go = ((size_t)(n0t + row) * CC + c0) * 2 + ch * 16;
                cpasync16(sbase + (uint32_t)(row * ROWB + ch * 16), gB + go);
            }
        };

        load_stageB(0, 0); CP_COMMIT();
        load_stageB(1, 1); CP_COMMIT();
        load_stageB(2, 2); CP_COMMIT();

        float acc[2][8][4];
#pragma unroll
        for (int i = 0; i < 2; ++i)
#pragma unroll
            for (int j = 0; j < 8; ++j)
#pragma unroll
                for (int k = 0; k < 4; ++k) acc[i][j][k] = 0.0f;

        const int wm = wid & 3;    // m strip (32 rows)
        const int wn = wid >> 2;   // n strip (64 cols)

        const uint32_t aOff = (uint32_t)((wm * 32 + (lane & 15)) * ROWA + (lane >> 4) * 16);
        const uint32_t bRow = (uint32_t)(wn * 64 + (lane & 7) + ((lane >> 4) << 3));
        const uint32_t bOff = bRow * ROWB + ((lane >> 3) & 1) * 16;

        for (int it = 0; it < TOTAL_IT; ++it) {
            CP_WAIT(2);
            __syncthreads();
            {
                int nit = it + 3;
                if (nit < TOTAL_IT) load_stageB(nit & 3, nit);
            }
            CP_COMMIT();

            const uint32_t sbase = sb + OFF_B + (uint32_t)(it & 3) * STG_B;
            const int kt = it & 7;
#pragma unroll
            for (int ks = 0; ks < 2; ++ks) {
                const uint32_t koffA = (uint32_t)(kt * 64 + ks * 32);
                const uint32_t koffB = (uint32_t)(ks * 32);

                uint32_t a[2][4], bh[4][4];
#pragma unroll
                for (int mt = 0; mt < 2; ++mt)
                    ldsm_x4(a[mt], sb + OFF_A + aOff + (uint32_t)mt * 16 * ROWA + koffA);
#pragma unroll
                for (int p = 0; p < 4; ++p)
                    ldsm_x4(bh[p], sbase + bOff + (uint32_t)p * 16 * ROWB + koffB);
#pragma unroll
                for (int mt = 0; mt < 2; ++mt)
#pragma unroll
                    for (int p = 0; p < 4; ++p) {
                        mma16816(acc[mt][2 * p],     a[mt], bh[p][0], bh[p][1]);
                        mma16816(acc[mt][2 * p + 1], a[mt], bh[p][2], bh[p][3]);
                    }
            }

            if (kt == 7) {
                const int n0t = n_base + (it >> 3) * BN;
#pragma unroll
                for (int mt = 0; mt < 2; ++mt) {
#pragma unroll
                    for (int h = 0; h < 2; ++h) {
                        int m = m0 + wm * 32 + mt * 16 + (lane >> 2) + h * 8;
                        float* orow = out + ((size_t)b * SS + m) * SS + n0t;
#pragma unroll
                        for (int nt = 0; nt < 8; ++nt) {
                            int n = wn * 64 + nt * 8 + (lane & 3) * 2;
                            float2 o;
                            o.x = fmaxf(acc[mt][nt][h * 2 + 0], 0.0f);
                            o.y = fmaxf(acc[mt][nt][h * 2 + 1], 0.0f);
                            *(float2*)&orow[n] = o;
                        }
                    }
                }
#pragma unroll
                for (int i = 0; i < 2; ++i)
#pragma unroll
                    for (int j = 0; j < 8; ++j)
#pragma unroll
                        for (int k = 0; k < 4; ++k) acc[i][j][k] = 0.0f;
            }
        }
    }
}

// ---------------------------------------------------------------------------
extern "C" void kernel_launch(void* const* d_in, const int* in_sizes, int n_in,
                              void* d_out, int out_size) {
    const float* src = (const float*)d_in[0];
    const float* dst = (const float*)d_in[1];
    float* out = (float*)d_out;

    cudaFuncSetAttribute(fused_kernel,
                         cudaFuncAttributeMaxDynamicSharedMemorySize, SMEM_TOTAL);

    fused_kernel<<<GRID_TOTAL, 256, SMEM_TOTAL>>>(src, dst, out);
}

// round 17
// speedup vs baseline: 1.3077x; 1.3077x over previous
#include <cuda_runtime.h>
#include <cuda_fp16.h>
#include <cstdint>

#define BB 8
#define CC 256
#define SS 2304

#define BM 128
#define BN 128
#define BKK 32
#define KITERS (CC / BKK)   // 8
#define NTILE 9             // n-tiles walked per CTA
#define TOTAL_IT (NTILE * KITERS)   // 72

// A region: 128 rows x 256 ch fp16 = 512B data/row, +16B pad (conflict-free)
#define ROWA 528
#define A_BYTES (BM * ROWA)              // 67584
// B stage: 128 rows x 32 ch fp16 = 64B data/row, padded to 80B
#define ROWB 80
#define STG_B (BN * ROWB)                // 10240
#define NSTAGE 4
#define OFF_A 0
#define OFF_B A_BYTES
#define SMEM_TOTAL (A_BYTES + NSTAGE * STG_B)   // 108544 (x2 CTAs = 212KB/SM)

// prep: 64-wide s tiles, 256ch x 67-float padded rows (conflict-free phase 2)
#define P_SW 64
#define P_PAD 67
#define P_SMEM (CC * P_PAD * 4)          // 68608

// ---------------- scratch (__device__ globals; no cudaMalloc allowed) ------
// Pre-normalized fp16 operands, K-major [B, S, C]
__device__ __half g_A[(size_t)BB * SS * CC];
__device__ __half g_B[(size_t)BB * SS * CC];

// ---------------- PTX helpers (base ISA only) -------------------------------
__device__ __forceinline__ uint32_t smem_u32(const void* p) {
    uint32_t a;
    asm("{ .reg .u64 t; cvta.to.shared.u64 t, %1; cvt.u32.u64 %0, t; }"
        : "=r"(a) : "l"(p));
    return a;
}
__device__ __forceinline__ void cpasync16(uint32_t dst, const void* src) {
    asm volatile("cp.async.cg.shared.global [%0], [%1], 16;"
                 :: "r"(dst), "l"(src) : "memory");
}
#define CP_COMMIT() asm volatile("cp.async.commit_group;" ::: "memory")
#define CP_WAIT(n)  asm volatile("cp.async.wait_group %0;" :: "n"(n) : "memory")

__device__ __forceinline__ void ldsm_x4(uint32_t* r, uint32_t addr) {
    asm volatile("ldmatrix.sync.aligned.m8n8.x4.shared.b16 {%0,%1,%2,%3}, [%4];"
                 : "=r"(r[0]), "=r"(r[1]), "=r"(r[2]), "=r"(r[3]) : "r"(addr));
}
__device__ __forceinline__ void mma16816(float* d, const uint32_t* a,
                                         uint32_t b0, uint32_t b1) {
    asm volatile(
        "mma.sync.aligned.m16n8k16.row.col.f32.f16.f16.f32 "
        "{%0,%1,%2,%3}, {%4,%5,%6,%7}, {%8,%9}, {%0,%1,%2,%3};"
        : "+f"(d[0]), "+f"(d[1]), "+f"(d[2]), "+f"(d[3])
        : "r"(a[0]), "r"(a[1]), "r"(a[2]), "r"(a[3]), "r"(b0), "r"(b1));
}

// ---------------------------------------------------------------------------
// Kernel 1 (v2): transpose + normalize + fp16 convert, 512 threads,
//   64-wide s tiles. Phase 1: 16 x LDG.64 per thread (float2 along s).
//   Phase 2: (s_local, cg) mapping, conflict-free LDS with 67-float pad.
//   Triggers programmatic launch completion for the dependent GEMM.
// ---------------------------------------------------------------------------
__global__ void __launch_bounds__(512)
prep_kernel(const float* __restrict__ src, const float* __restrict__ dst) {
    extern __shared__ float tile[];       // [CC][P_PAD]
    const int z = blockIdx.y;
    const int b = z >> 1, which = z & 1;
    const float* in = which ? dst : src;
    __half* outp = which ? g_B : g_A;
    const int s0 = blockIdx.x * P_SW;
    const int tid = threadIdx.x;

    // phase 1: 256 rows x 64 s; thread (rg = tid>>5, l2 = tid&31)
    {
        const int l2 = tid & 31;          // float2 index within row
        const int rg = tid >> 5;          // 0..15
        const float* p = in + (size_t)b * CC * SS + s0 + l2 * 2;
#pragma unroll
        for (int i = 0; i < 16; ++i) {
            int row = rg + i * 16;
            float2 v = *(const float2*)&p[(size_t)row * SS];
            tile[row * P_PAD + l2 * 2]     = v.x;
            tile[row * P_PAD + l2 * 2 + 1] = v.y;
        }
    }
    __syncthreads();

    // phase 2: 512 threads = 64 s x 8 channel-groups (4 ch each)
    const int s_local = tid >> 3;
    const int cg = tid & 7;

    float v[32];
    float sq = 0.0f;
#pragma unroll
    for (int t = 0; t < 8; ++t)
#pragma unroll
        for (int j = 0; j < 4; ++j) {
            float x = tile[(t * 32 + cg * 4 + j) * P_PAD + s_local];
            v[t * 4 + j] = x;
            sq = fmaf(x, x, sq);
        }
    sq += __shfl_xor_sync(0xffffffffu, sq, 1);
    sq += __shfl_xor_sync(0xffffffffu, sq, 2);
    sq += __shfl_xor_sync(0xffffffffu, sq, 4);
    const float inv = rsqrtf(sq);

    __half* orow = outp + ((size_t)b * SS + s0 + s_local) * CC + cg * 4;
#pragma unroll
    for (int t = 0; t < 8; ++t) {
        __half2 h01 = __floats2half2_rn(v[t * 4 + 0] * inv, v[t * 4 + 1] * inv);
        __half2 h23 = __floats2half2_rn(v[t * 4 + 2] * inv, v[t * 4 + 3] * inv);
        uint2 pack = make_uint2(*(uint32_t*)&h01, *(uint32_t*)&h23);
        *(uint2*)&orow[t * 32] = pack;
    }

#if __CUDA_ARCH__ >= 900
    // allow the dependent GEMM grid to begin launching (its griddepsync
    // still orders all dependent loads after this grid's completion+flush)
    cudaTriggerProgrammaticLaunchCompletion();
#endif
}

// ---------------------------------------------------------------------------
// Kernel 2: HMMA GEMM, persistent-n CTAs (R14/15 verified core).
//   256 threads (8 warps, 4m x 2n), warp tile 32x64, occupancy 2.
//   A tile resident in SMEM for 9 n-tiles; B streams via 4-stage cp.async.
//   Grid 2 x 18 x 8 = 288 CTAs = one wave. PDL: waits on prep via
//   cudaGridDependencySynchronize before any dependent load.
// ---------------------------------------------------------------------------
__global__ void __launch_bounds__(256, 2)
corr_mma_kernel(float* __restrict__ out) {
    extern __shared__ char smem[];
    uint32_t sb = smem_u32(smem);

    const int tid  = threadIdx.x;
    const int lane = tid & 31;
    const int wid  = tid >> 5;
    const int b      = blockIdx.z;
    const int m0     = blockIdx.y * BM;
    const int n_base = blockIdx.x * (NTILE * BN);   // 0 or 1152

    const char* gA = (const char*)(g_A + (size_t)b * SS * CC);
    const char* gB = (const char*)(g_B + (size_t)b * SS * CC);

#if __CUDA_ARCH__ >= 900
    cudaGridDependencySynchronize();   // prep grid complete + memory visible
#endif

    // ---- A fill (once): 128 rows x 512B = 4096 x 16B chunks, 16/thread
#pragma unroll
    for (int i = 0; i < 16; ++i) {
        int u = tid + i * 256;
        int row = u >> 5, ch = u & 31;
        size_t go = ((size_t)(m0 + row) * CC) * 2 + ch * 16;
        cpasync16(sb + OFF_A + (uint32_t)(row * ROWA + ch * 16), gA + go);
    }
    CP_COMMIT();

    // ---- B stage loader: 128 rows x 64B = 512 x 16B chunks, 2/thread
    auto load_stageB = [&](int st, int it) {
        uint32_t sbase = sb + OFF_B + (uint32_t)st * STG_B;
        int n0t = n_base + (it >> 3) * BN;
        int c0  = (it & 7) * BKK;
#pragma unroll
        for (int i = 0; i < 2; ++i) {
            int u = tid + i * 256;             // [0,512)
            int row = u >> 2, ch = u & 3;
            size_t go = ((size_t)(n0t + row) * CC + c0) * 2 + ch * 16;
            cpasync16(sbase + (uint32_t)(row * ROWB + ch * 16), gB + go);
        }
    };

    load_stageB(0, 0); CP_COMMIT();
    load_stageB(1, 1); CP_COMMIT();
    load_stageB(2, 2); CP_COMMIT();

    float acc[2][8][4];
#pragma unroll
    for (int i = 0; i < 2; ++i)
#pragma unroll
        for (int j = 0; j < 8; ++j)
#pragma unroll
            for (int k = 0; k < 4; ++k) acc[i][j][k] = 0.0f;

    const int wm = wid & 3;    // m strip (32 rows)
    const int wn = wid >> 2;   // n strip (64 cols)

    const uint32_t aOff = (uint32_t)((wm * 32 + (lane & 15)) * ROWA + (lane >> 4) * 16);
    const uint32_t bRow = (uint32_t)(wn * 64 + (lane & 7) + ((lane >> 4) << 3));
    const uint32_t bOff = bRow * ROWB + ((lane >> 3) & 1) * 16;

    for (int it = 0; it < TOTAL_IT; ++it) {
        CP_WAIT(2);
        __syncthreads();
        {
            int nit = it + 3;
            if (nit < TOTAL_IT) load_stageB(nit & 3, nit);
        }
        CP_COMMIT();

        const uint32_t sbase = sb + OFF_B + (uint32_t)(it & 3) * STG_B;
        const int kt = it & 7;
#pragma unroll
        for (int ks = 0; ks < 2; ++ks) {
            const uint32_t koffA = (uint32_t)(kt * 64 + ks * 32);
            const uint32_t koffB = (uint32_t)(ks * 32);

            uint32_t a[2][4], bh[4][4];
#pragma unroll
            for (int mt = 0; mt < 2; ++mt)
                ldsm_x4(a[mt], sb + OFF_A + aOff + (uint32_t)mt * 16 * ROWA + koffA);
#pragma unroll
            for (int p = 0; p < 4; ++p)
                ldsm_x4(bh[p], sbase + bOff + (uint32_t)p * 16 * ROWB + koffB);
#pragma unroll
            for (int mt = 0; mt < 2; ++mt)
#pragma unroll
                for (int p = 0; p < 4; ++p) {
                    mma16816(acc[mt][2 * p],     a[mt], bh[p][0], bh[p][1]);
                    mma16816(acc[mt][2 * p + 1], a[mt], bh[p][2], bh[p][3]);
                }
        }

        if (kt == 7) {
            // ---- epilogue for this n-tile: ReLU + float2 stores, then reset
            const int n0t = n_base + (it >> 3) * BN;
#pragma unroll
            for (int mt = 0; mt < 2; ++mt) {
#pragma unroll
                for (int h = 0; h < 2; ++h) {
                    int m = m0 + wm * 32 + mt * 16 + (lane >> 2) + h * 8;
                    float* orow = out + ((size_t)b * SS + m) * SS + n0t;
#pragma unroll
                    for (int nt = 0; nt < 8; ++nt) {
                        int n = wn * 64 + nt * 8 + (lane & 3) * 2;
                        float2 o;
                        o.x = fmaxf(acc[mt][nt][h * 2 + 0], 0.0f);
                        o.y = fmaxf(acc[mt][nt][h * 2 + 1], 0.0f);
                        *(float2*)&orow[n] = o;
                    }
                }
            }
#pragma unroll
            for (int i = 0; i < 2; ++i)
#pragma unroll
                for (int j = 0; j < 8; ++j)
#pragma unroll
                    for (int k = 0; k < 4; ++k) acc[i][j][k] = 0.0f;
        }
    }
}

// ---------------------------------------------------------------------------
extern "C" void kernel_launch(void* const* d_in, const int* in_sizes, int n_in,
                              void* d_out, int out_size) {
    const float* src = (const float*)d_in[0];
    const float* dst = (const float*)d_in[1];
    float* out = (float*)d_out;

    cudaFuncSetAttribute(prep_kernel,
                         cudaFuncAttributeMaxDynamicSharedMemorySize, P_SMEM);
    cudaFuncSetAttribute(corr_mma_kernel,
                         cudaFuncAttributeMaxDynamicSharedMemorySize, SMEM_TOTAL);

    prep_kernel<<<dim3(SS / P_SW, 2 * BB), 512, P_SMEM>>>(src, dst);

    // GEMM with programmatic dependent launch (overlaps launch latency with
    // prep tail; griddepsync inside the kernel enforces data ordering).
    cudaLaunchConfig_t cfg = {};
    cfg.gridDim = dim3(2, SS / BM, BB);
    cfg.blockDim = dim3(256, 1, 1);
    cfg.dynamicSmemBytes = SMEM_TOTAL;
    cfg.stream = 0;
    cudaLaunchAttribute attrs[1];
    attrs[0].id = cudaLaunchAttributeProgrammaticStreamSerialization;
    attrs[0].val.programmaticStreamSerializationAllowed = 1;
    cfg.attrs = attrs;
    cfg.numAttrs = 1;
    cudaLaunchKernelEx(&cfg, corr_mma_kernel, out);
}